// round 10
// baseline (speedup 1.0000x reference)
#include <cuda_runtime.h>
#include <cstdint>

// PCEN, 1 row per CTA (grid = 8192), 6 CTAs/SM. Row loaded as FOUR 8KB bulk
// copies (separate mbarriers); each warp waits only on the quarter(s) that
// cover its 800-element span, so compute starts as soon as the first 8KB
// lands. Per-warp eager bulk stores; L2 evict_first hints. EMA in w-scaled
// space (s = ema/w); pass-2 specialized on warp-uniform rhalf.
//   out = (x / (FLOOR+ema)^a + d)^(1/root) - d^(1/root)

constexpr int      kT         = 8000;
constexpr int      kChunk     = 25;            // 320*25 = 8000; 25 coprime 32 -> no bank conflicts
constexpr int      kThreads   = 320;
constexpr int      kWarps     = kThreads / 32; // 10
constexpr float    kFloor     = 1e-6f;
constexpr int      kQElems    = kT / 4;                    // 2000 elements / quarter
constexpr unsigned kQBytes    = kQElems * 4;               // 8000 bytes
constexpr unsigned kWarpBytes = 32 * kChunk * 4;           // 3200 per-warp store

__device__ __forceinline__ uint32_t s2u(const void* p) {
    return (uint32_t)__cvta_generic_to_shared(p);
}

__device__ __forceinline__ float sqrt_apx(float v) {
    float r;
    asm("sqrt.approx.f32 %0, %1;" : "=f"(r) : "f"(v));
    return r;
}

__device__ __forceinline__ float rcp_apx(float v) {
    float r;
    asm("rcp.approx.f32 %0, %1;" : "=f"(r) : "f"(v));
    return r;
}

__device__ __forceinline__ uint64_t evict_first_policy() {
    uint64_t pol;
    asm("createpolicy.fractional.L2::evict_first.b64 %0, 1.0;" : "=l"(pol));
    return pol;
}

__device__ __forceinline__ void bulk_load_hint(uint32_t dst_smem, const void* src_gmem,
                                               uint32_t bytes, uint32_t mbar, uint64_t pol) {
    asm volatile(
        "cp.async.bulk.shared::cta.global.mbarrier::complete_tx::bytes.L2::cache_hint"
        " [%0], [%1], %2, [%3], %4;"
        :: "r"(dst_smem), "l"(src_gmem), "r"(bytes), "r"(mbar), "l"(pol) : "memory");
}

__device__ __forceinline__ void mbar_expect_tx(uint32_t mbar, uint32_t bytes) {
    asm volatile("mbarrier.arrive.expect_tx.shared::cta.b64 _, [%0], %1;"
                 :: "r"(mbar), "r"(bytes) : "memory");
}

__device__ __forceinline__ void mbar_wait(uint32_t mbar, uint32_t phase) {
    asm volatile(
        "{\n\t.reg .pred P;\n"
        "W_%=:\n\t"
        "mbarrier.try_wait.parity.acquire.cta.shared::cta.b64 P, [%0], %1, 0x989680;\n\t"
        "@!P bra W_%=;\n\t}"
        :: "r"(mbar), "r"(phase) : "memory");
}

__global__ void __launch_bounds__(kThreads, 6)
pcen_kernel(const float* __restrict__ x,
            const float* __restrict__ alpha,
            const float* __restrict__ delta,
            const float* __restrict__ root,
            const float* __restrict__ ew,
            float* __restrict__ out,
            int C)
{
    __shared__ float sx[kT];
    __shared__ __align__(8) unsigned long long mbar[4];
    __shared__ float sA[kWarps], sB[kWarps];

    const int tid  = threadIdx.x;
    const int lane = tid & 31;
    const int wid  = tid >> 5;
    const int row  = blockIdx.x;

    const uint64_t pol = evict_first_policy();

    // kick off all four quarter-row loads ASAP
    if (tid == 0) {
        const float* src = x + (size_t)row * kT;
        #pragma unroll
        for (int qi = 0; qi < 4; ++qi) {
            const uint32_t mb = s2u(&mbar[qi]);
            asm volatile("mbarrier.init.shared::cta.b64 [%0], 1;" :: "r"(mb) : "memory");
            mbar_expect_tx(mb, kQBytes);
            bulk_load_hint(s2u(sx + qi * kQElems), src + qi * kQElems, kQBytes, mb, pol);
        }
    }

    // per-row params (warp-uniform); overlaps the bulk-load latency
    const int   c  = row % C;
    const float w  = fminf(fmaxf(ew[c], 0.0f), 1.0f);
    const float q  = 1.0f - w;
    const float a  = fminf(alpha[c], 1.0f);
    const float d  = delta[c];
    const float r  = 1.0f / fmaxf(root[c], 1.0f);
    const bool  rhalf = (r == 0.5f);
    const float dr = rhalf ? sqrt_apx(d) : __powf(d, r);
    const float na = -a;
    const float winv = rcp_apx(fmaxf(w, 1e-30f));   // s-space: s = ema / w

    // make mbar init visible to all threads
    __syncthreads();

    // wait only for the quarter(s) covering this warp's 800-element span.
    // warp w spans [800w, 800w+800): quarters q_lo = 800w/2000, q_hi = (800w+799)/2000.
    {
        const int qlo = (wid * 800) / kQElems;
        const int qhi = (wid * 800 + 799) / kQElems;
        mbar_wait(s2u(&mbar[qlo]), 0);
        if (qhi != qlo) mbar_wait(s2u(&mbar[qhi]), 0);
    }

    const int off = tid * kChunk;

    // pass 1: per-thread affine reduce over the 25-element chunk (s-space)
    float b = 0.0f;
    #pragma unroll
    for (int k = 0; k < kChunk; ++k)
        b = fmaf(q, b, sx[off + k]);
    const float q2 = q*q, q4 = q2*q2, q8 = q4*q4, q16 = q8*q8;
    float A = q16 * q8 * q;   // q^25

    // warp inclusive scan of (A,b)
    #pragma unroll
    for (int s = 1; s < 32; s <<= 1) {
        float Ap = __shfl_up_sync(0xffffffffu, A, s);
        float bp = __shfl_up_sync(0xffffffffu, b, s);
        if (lane >= s) { b = fmaf(A, bp, b); A *= Ap; }
    }
    if (lane == 31) { sA[wid] = A; sB[wid] = b; }
    __syncthreads();

    // every warp redundantly scans the 10 warp aggregates (single barrier)
    float Aw = (lane < kWarps) ? sA[lane] : 1.0f;
    float bw = (lane < kWarps) ? sB[lane] : 0.0f;
    #pragma unroll
    for (int s = 1; s < 16; s <<= 1) {
        float Ap = __shfl_up_sync(0xffffffffu, Aw, s);
        float bp = __shfl_up_sync(0xffffffffu, bw, s);
        if (lane >= s) { bw = fmaf(Aw, bp, bw); Aw *= Ap; }
    }
    const int src = (wid > 0) ? (wid - 1) : 0;
    float ApX = __shfl_sync(0xffffffffu, Aw, src);
    float bpX = __shfl_sync(0xffffffffu, bw, src);
    if (wid == 0) { ApX = 1.0f; bpX = 0.0f; }

    // thread-exclusive prefix within warp, composed with warp prefix
    float Ai = __shfl_up_sync(0xffffffffu, A, 1);
    float bi = __shfl_up_sync(0xffffffffu, b, 1);
    if (lane == 0) { Ai = 1.0f; bi = 0.0f; }
    const float Aex = Ai * ApX;
    const float bex = fmaf(Ai, bpX, bi);
    // sx[0] is safe here: warp 0 passed its quarter-0 wait before the
    // __syncthreads above, which orders+publishes the data CTA-wide.
    const float s0  = sx[0] * winv;       // s-space init (ema_0 = x0)
    float acc = fmaf(Aex, s0, bex);       // exact carry (s-space) into this chunk

    // pass 2: EMA recompute (s-space) + pointwise PCEN, specialized on rhalf
    if (rhalf) {
        #pragma unroll
        for (int k = 0; k < kChunk; ++k) {
            const float xv = sx[off + k];
            acc = fmaf(q, acc, xv);                        // s_t
            const float v = fmaf(w, acc, kFloor);          // FLOOR + ema_t
            const float p = __powf(v, na);                 // lg2 + mul + ex2
            const float u = fmaf(xv, p, d);
            sx[off + k] = sqrt_apx(u) - dr;                // 1 MUFU
        }
    } else {
        #pragma unroll
        for (int k = 0; k < kChunk; ++k) {
            const float xv = sx[off + k];
            acc = fmaf(q, acc, xv);
            const float v = fmaf(w, acc, kFloor);
            const float p = __powf(v, na);
            const float u = fmaf(xv, p, d);
            sx[off + k] = __powf(u, r) - dr;
        }
    }

    // per-warp eager bulk store: drain this warp's 3200B as soon as it's done
    __syncwarp();
    if (lane == 0) {
        asm volatile("fence.proxy.async.shared::cta;" ::: "memory");
        asm volatile(
            "cp.async.bulk.global.shared::cta.bulk_group.L2::cache_hint [%0], [%1], %2, %3;"
            :: "l"(out + (size_t)row * kT + wid * (32 * kChunk)),
               "r"(s2u(sx + wid * (32 * kChunk))), "r"(kWarpBytes), "l"(pol)
            : "memory");
        asm volatile("cp.async.bulk.commit_group;" ::: "memory");
        // smem must stay valid until the store has read it
        asm volatile("cp.async.bulk.wait_group.read 0;" ::: "memory");
    }
}

extern "C" void kernel_launch(void* const* d_in, const int* in_sizes, int n_in,
                              void* d_out, int out_size)
{
    const float* x     = (const float*)d_in[0];
    const float* alpha = (const float*)d_in[1];
    const float* delta = (const float*)d_in[2];
    const float* root  = (const float*)d_in[3];
    const float* ew    = (const float*)d_in[4];
    float* out = (float*)d_out;

    const int C    = in_sizes[1];            // 64
    const int rows = in_sizes[0] / kT;       // 8192

    static bool configured = false;
    if (!configured) {
        cudaFuncSetAttribute(pcen_kernel,
                             cudaFuncAttributePreferredSharedMemoryCarveout, 100);
        configured = true;
    }

    pcen_kernel<<<rows, kThreads>>>(x, alpha, delta, root, ew, out, C);
}

// round 11
// speedup vs baseline: 1.0023x; 1.0023x over previous
#include <cuda_runtime.h>
#include <cstdint>

// PCEN, 1 row per CTA (grid = 8192), 6 CTAs/SM. Row loaded as two 16KB bulk
// copies (separate mbarriers, per-half waits). SINGLE full-row 32KB bulk
// store (long write burst, fewer HBM R/W turnarounds) — isolating write
// burst length vs R9's 10x 3.2KB eager stores. L2 evict_first hints.
// EMA in w-scaled space (s = ema/w); pass-2 specialized on rhalf.
//   out = (x / (FLOOR+ema)^a + d)^(1/root) - d^(1/root)

constexpr int      kT         = 8000;
constexpr int      kChunk     = 25;            // 320*25 = 8000; 25 coprime 32 -> no bank conflicts
constexpr int      kThreads   = 320;
constexpr int      kWarps     = kThreads / 32; // 10
constexpr float    kFloor     = 1e-6f;
constexpr int      kHalfElems = kT / 2;                    // 4000
constexpr unsigned kHalfBytes = kHalfElems * 4;            // 16000
constexpr unsigned kRowBytes  = kT * 4;                    // 32000

__device__ __forceinline__ uint32_t s2u(const void* p) {
    return (uint32_t)__cvta_generic_to_shared(p);
}

__device__ __forceinline__ float sqrt_apx(float v) {
    float r;
    asm("sqrt.approx.f32 %0, %1;" : "=f"(r) : "f"(v));
    return r;
}

__device__ __forceinline__ float rcp_apx(float v) {
    float r;
    asm("rcp.approx.f32 %0, %1;" : "=f"(r) : "f"(v));
    return r;
}

__device__ __forceinline__ uint64_t evict_first_policy() {
    uint64_t pol;
    asm("createpolicy.fractional.L2::evict_first.b64 %0, 1.0;" : "=l"(pol));
    return pol;
}

__device__ __forceinline__ void bulk_load_hint(uint32_t dst_smem, const void* src_gmem,
                                               uint32_t bytes, uint32_t mbar, uint64_t pol) {
    asm volatile(
        "cp.async.bulk.shared::cta.global.mbarrier::complete_tx::bytes.L2::cache_hint"
        " [%0], [%1], %2, [%3], %4;"
        :: "r"(dst_smem), "l"(src_gmem), "r"(bytes), "r"(mbar), "l"(pol) : "memory");
}

__device__ __forceinline__ void mbar_expect_tx(uint32_t mbar, uint32_t bytes) {
    asm volatile("mbarrier.arrive.expect_tx.shared::cta.b64 _, [%0], %1;"
                 :: "r"(mbar), "r"(bytes) : "memory");
}

__device__ __forceinline__ void mbar_wait(uint32_t mbar, uint32_t phase) {
    asm volatile(
        "{\n\t.reg .pred P;\n"
        "W_%=:\n\t"
        "mbarrier.try_wait.parity.acquire.cta.shared::cta.b64 P, [%0], %1, 0x989680;\n\t"
        "@!P bra W_%=;\n\t}"
        :: "r"(mbar), "r"(phase) : "memory");
}

__global__ void __launch_bounds__(kThreads, 6)
pcen_kernel(const float* __restrict__ x,
            const float* __restrict__ alpha,
            const float* __restrict__ delta,
            const float* __restrict__ root,
            const float* __restrict__ ew,
            float* __restrict__ out,
            int C)
{
    __shared__ float sx[kT];
    __shared__ __align__(8) unsigned long long mbar[2];
    __shared__ float sA[kWarps], sB[kWarps];

    const int tid  = threadIdx.x;
    const int lane = tid & 31;
    const int wid  = tid >> 5;
    const int row  = blockIdx.x;

    const uint64_t pol = evict_first_policy();

    // kick off both half-row loads ASAP
    if (tid == 0) {
        const uint32_t mb0 = s2u(&mbar[0]);
        const uint32_t mb1 = s2u(&mbar[1]);
        asm volatile("mbarrier.init.shared::cta.b64 [%0], 1;" :: "r"(mb0) : "memory");
        asm volatile("mbarrier.init.shared::cta.b64 [%0], 1;" :: "r"(mb1) : "memory");
        const float* src = x + (size_t)row * kT;
        mbar_expect_tx(mb0, kHalfBytes);
        bulk_load_hint(s2u(sx), src, kHalfBytes, mb0, pol);
        mbar_expect_tx(mb1, kHalfBytes);
        bulk_load_hint(s2u(sx + kHalfElems), src + kHalfElems, kHalfBytes, mb1, pol);
    }

    // per-row params (warp-uniform); overlaps the bulk-load latency
    const int   c  = row % C;
    const float w  = fminf(fmaxf(ew[c], 0.0f), 1.0f);
    const float q  = 1.0f - w;
    const float a  = fminf(alpha[c], 1.0f);
    const float d  = delta[c];
    const float r  = 1.0f / fmaxf(root[c], 1.0f);
    const bool  rhalf = (r == 0.5f);
    const float dr = rhalf ? sqrt_apx(d) : __powf(d, r);
    const float na = -a;
    const float winv = rcp_apx(fmaxf(w, 1e-30f));   // s-space: s = ema / w

    // make mbar init visible to all threads, then wait only for OUR half
    __syncthreads();
    mbar_wait(s2u(&mbar[wid < (kWarps / 2) ? 0 : 1]), 0);

    const int off = tid * kChunk;

    // pass 1: per-thread affine reduce over the 25-element chunk (s-space)
    float b = 0.0f;
    #pragma unroll
    for (int k = 0; k < kChunk; ++k)
        b = fmaf(q, b, sx[off + k]);
    const float q2 = q*q, q4 = q2*q2, q8 = q4*q4, q16 = q8*q8;
    float A = q16 * q8 * q;   // q^25

    // warp inclusive scan of (A,b)
    #pragma unroll
    for (int s = 1; s < 32; s <<= 1) {
        float Ap = __shfl_up_sync(0xffffffffu, A, s);
        float bp = __shfl_up_sync(0xffffffffu, b, s);
        if (lane >= s) { b = fmaf(A, bp, b); A *= Ap; }
    }
    if (lane == 31) { sA[wid] = A; sB[wid] = b; }
    __syncthreads();

    // every warp redundantly scans the 10 warp aggregates (single barrier)
    float Aw = (lane < kWarps) ? sA[lane] : 1.0f;
    float bw = (lane < kWarps) ? sB[lane] : 0.0f;
    #pragma unroll
    for (int s = 1; s < 16; s <<= 1) {
        float Ap = __shfl_up_sync(0xffffffffu, Aw, s);
        float bp = __shfl_up_sync(0xffffffffu, bw, s);
        if (lane >= s) { bw = fmaf(Aw, bp, bw); Aw *= Ap; }
    }
    const int src = (wid > 0) ? (wid - 1) : 0;
    float ApX = __shfl_sync(0xffffffffu, Aw, src);
    float bpX = __shfl_sync(0xffffffffu, bw, src);
    if (wid == 0) { ApX = 1.0f; bpX = 0.0f; }

    // thread-exclusive prefix within warp, composed with warp prefix
    float Ai = __shfl_up_sync(0xffffffffu, A, 1);
    float bi = __shfl_up_sync(0xffffffffu, b, 1);
    if (lane == 0) { Ai = 1.0f; bi = 0.0f; }
    const float Aex = Ai * ApX;
    const float bex = fmaf(Ai, bpX, bi);
    const float s0  = sx[0] * winv;       // s-space init (ema_0 = x0)
    float acc = fmaf(Aex, s0, bex);       // exact carry (s-space) into this chunk

    // pass 2: EMA recompute (s-space) + pointwise PCEN, specialized on rhalf
    if (rhalf) {
        #pragma unroll
        for (int k = 0; k < kChunk; ++k) {
            const float xv = sx[off + k];
            acc = fmaf(q, acc, xv);                        // s_t
            const float v = fmaf(w, acc, kFloor);          // FLOOR + ema_t
            const float p = __powf(v, na);                 // lg2 + mul + ex2
            const float u = fmaf(xv, p, d);
            sx[off + k] = sqrt_apx(u) - dr;                // 1 MUFU
        }
    } else {
        #pragma unroll
        for (int k = 0; k < kChunk; ++k) {
            const float xv = sx[off + k];
            acc = fmaf(q, acc, xv);
            const float v = fmaf(w, acc, kFloor);
            const float p = __powf(v, na);
            const float u = fmaf(xv, p, d);
            sx[off + k] = __powf(u, r) - dr;
        }
    }

    // single full-row bulk store: one long 32KB write burst per CTA
    __syncthreads();
    if (tid == 0) {
        asm volatile("fence.proxy.async.shared::cta;" ::: "memory");
        asm volatile(
            "cp.async.bulk.global.shared::cta.bulk_group.L2::cache_hint [%0], [%1], %2, %3;"
            :: "l"(out + (size_t)row * kT), "r"(s2u(sx)), "r"(kRowBytes), "l"(pol)
            : "memory");
        asm volatile("cp.async.bulk.commit_group;" ::: "memory");
        // smem must stay valid until the store has read it
        asm volatile("cp.async.bulk.wait_group.read 0;" ::: "memory");
    }
}

extern "C" void kernel_launch(void* const* d_in, const int* in_sizes, int n_in,
                              void* d_out, int out_size)
{
    const float* x     = (const float*)d_in[0];
    const float* alpha = (const float*)d_in[1];
    const float* delta = (const float*)d_in[2];
    const float* root  = (const float*)d_in[3];
    const float* ew    = (const float*)d_in[4];
    float* out = (float*)d_out;

    const int C    = in_sizes[1];            // 64
    const int rows = in_sizes[0] / kT;       // 8192

    static bool configured = false;
    if (!configured) {
        cudaFuncSetAttribute(pcen_kernel,
                             cudaFuncAttributePreferredSharedMemoryCarveout, 100);
        configured = true;
    }

    pcen_kernel<<<rows, kThreads>>>(x, alpha, delta, root, ew, out, C);
}